// round 2
// baseline (speedup 1.0000x reference)
#include <cuda_runtime.h>
#include <stdint.h>

// Problem constants (fixed by the dataset)
#define T_  500
#define B_  16
#define S_  256
#define P_  128
#define L_  16

#define CAP 100      // per-(lang,p) index capacity; stride 25 words -> bank-conflict-free u32 reads
#define TT  4        // t-tile per CTA (float4 gather)
#define PADV (-3.402823466e38f)

// CSR scratch: __device__ globals (no allocation allowed in kernel_launch)
__device__ unsigned char g_idx[L_ * P_ * CAP];
__device__ int           g_cnt[L_ * P_];

// ---------------------------------------------------------------------------
// Prologue: build per-(lang, p) sparse index lists from the 0/1 matrices.
// One thread per (lang, p). Reads are coalesced across p (stride-1).
// Lists are padded to a multiple of 4 by duplicating the last valid index
// (idempotent under max), so the main loop needs no tail handling.
// Pure function of mats -> safe to replay every graph iteration.
// ---------------------------------------------------------------------------
__global__ void build_csr_kernel(const float* __restrict__ mats) {
    int lp = blockIdx.x * blockDim.x + threadIdx.x;
    if (lp >= L_ * P_) return;
    int l = lp >> 7;          // / P_
    int p = lp & (P_ - 1);    // % P_

    const float* base = mats + (size_t)l * S_ * P_ + p;
    unsigned char* lst = g_idx + (size_t)lp * CAP;

    int cnt = 0;
    #pragma unroll 4
    for (int s = 0; s < S_; ++s) {
        float v = base[(size_t)s * P_];
        if (v != 0.0f) {
            if (cnt < CAP) lst[cnt] = (unsigned char)s;
            ++cnt;
        }
    }
    if (cnt > CAP) cnt = CAP;

    int rc = (cnt + 3) & ~3;
    unsigned char fill = (cnt > 0) ? lst[cnt - 1] : (unsigned char)0;
    for (int i = cnt; i < rc; ++i) lst[i] = fill;

    g_cnt[lp] = cnt;
}

// ---------------------------------------------------------------------------
// Main kernel: CTA = (t-tile of 4, batch b). 128 threads, thread = phoneme p.
// SMEM:
//   sl   : logits transposed [s][TT]  -> one LDS.128 gather serves 4 t's
//   sidx : this language's CSR index lists (u8), stride CAP=100
//   scnt : list lengths
// ---------------------------------------------------------------------------
__global__ __launch_bounds__(P_) void allophone_map_kernel(
    const float* __restrict__ logits,      // [T, B, S]
    const int*   __restrict__ lang_ids,    // [B]
    float*       __restrict__ out)         // [T, B, P]
{
    __shared__ float          sl[S_ * TT];       // 4 KB
    __shared__ unsigned char  sidx[P_ * CAP];    // 12.8 KB
    __shared__ int            scnt[P_];

    const int b   = blockIdx.y;
    const int t0  = blockIdx.x * TT;
    const int tid = threadIdx.x;

    const int lang = __ldg(lang_ids + b);

    // Load this language's CSR lists into SMEM (bulk uint4 copy: 12800 B)
    {
        const uint4* src = (const uint4*)(g_idx + (size_t)lang * P_ * CAP);
        uint4*       dst = (uint4*)sidx;
        #pragma unroll
        for (int i = tid; i < (P_ * CAP) / 16; i += P_) dst[i] = src[i];
        scnt[tid] = g_cnt[lang * P_ + tid];
    }

    // Load logits tile, transposed: sl[s*TT + t] = logits[t0+t, b, s]
    {
        #pragma unroll
        for (int i = tid; i < TT * S_; i += P_) {
            int t = i >> 8;           // / S_
            int s = i & (S_ - 1);     // % S_
            sl[s * TT + t] = logits[((size_t)(t0 + t) * B_ + b) * S_ + s];
        }
    }
    __syncthreads();

    const int p  = tid;
    const int rc = (scnt[p] + 3) & ~3;            // padded length
    const bool empty = (scnt[p] == 0);
    const uint32_t* wlst = (const uint32_t*)(sidx + p * CAP);

    float a0 = PADV, a1 = PADV, a2 = PADV, a3 = PADV;

    for (int i = 0; i < rc; i += 4) {
        uint32_t w = wlst[i >> 2];
        #pragma unroll
        for (int k = 0; k < 4; ++k) {
            int s = (w >> (8 * k)) & 0xFF;
            float4 v = *(const float4*)(sl + s * TT);
            a0 = fmaxf(a0, v.x);
            a1 = fmaxf(a1, v.y);
            a2 = fmaxf(a2, v.z);
            a3 = fmaxf(a3, v.w);
        }
    }
    if (empty) { a0 = a1 = a2 = a3 = PADV; }

    // Write out[t0+t, b, p] — coalesced across p
    out[((size_t)(t0 + 0) * B_ + b) * P_ + p] = a0;
    out[((size_t)(t0 + 1) * B_ + b) * P_ + p] = a1;
    out[((size_t)(t0 + 2) * B_ + b) * P_ + p] = a2;
    out[((size_t)(t0 + 3) * B_ + b) * P_ + p] = a3;
}

// ---------------------------------------------------------------------------
extern "C" void kernel_launch(void* const* d_in, const int* in_sizes, int n_in,
                              void* d_out, int out_size) {
    const float* logits = (const float*)d_in[0];   // [T,B,S] f32
    const int*   langs  = (const int*)  d_in[1];   // [B] i32
    const float* mats   = (const float*)d_in[2];   // [L,S,P] f32
    // d_in[3] (mask) is redundant: mask == (mats == 0)

    build_csr_kernel<<<(L_ * P_ + 127) / 128, 128>>>(mats);

    dim3 grid(T_ / TT, B_);   // 125 x 16
    allophone_map_kernel<<<grid, P_>>>(logits, langs, (float*)d_out);
}

// round 3
// speedup vs baseline: 3.6679x; 3.6679x over previous
#include <cuda_runtime.h>
#include <stdint.h>

// Problem constants (fixed by the dataset)
#define T_  500
#define B_  16
#define S_  256
#define P_  128
#define L_  16

#define TT   4        // t-tile per CTA (float4 gather)
#define NW   (S_ / 32)   // 8 mask words per (lang, p)
#define PADV (-3.402823466e38f)

// Bitmask scratch: [L][NW][P] u32 — word-major so main-kernel reads are coalesced.
__device__ uint32_t g_bits[L_ * NW * P_];

// ---------------------------------------------------------------------------
// Build: CTA = (lang, s-chunk of 32). 128 threads = p. Each thread makes one
// 32-bit membership word from 32 independent, fully-coalesced loads.
// Pure function of mats -> safe to replay every graph iteration.
// ---------------------------------------------------------------------------
__global__ __launch_bounds__(P_) void build_bits_kernel(const float* __restrict__ mats) {
    const int l = blockIdx.x >> 3;        // / NW
    const int w = blockIdx.x & (NW - 1);  // % NW
    const int p = threadIdx.x;

    const float* base = mats + ((size_t)l * S_ + w * 32) * P_ + p;

    uint32_t word = 0;
    #pragma unroll
    for (int j = 0; j < 32; ++j) {
        float v = base[(size_t)j * P_];          // coalesced across p
        word |= (v != 0.0f ? 1u : 0u) << j;
    }
    g_bits[(l * NW + w) * P_ + p] = word;        // coalesced
}

// ---------------------------------------------------------------------------
// Main: CTA = (t-tile of 4, batch b). 128 threads = phoneme p.
// smem: logits transposed [s][TT] -> one LDS.128 gather serves 4 t's.
// Membership comes from the bitmask (L1-resident, coalesced reads).
// ---------------------------------------------------------------------------
__global__ __launch_bounds__(P_) void allophone_map_kernel(
    const float* __restrict__ logits,      // [T, B, S]
    const int*   __restrict__ lang_ids,    // [B]
    float*       __restrict__ out)         // [T, B, P]
{
    __shared__ float sl[S_ * TT];          // 4 KB

    const int b   = blockIdx.y;
    const int t0  = blockIdx.x * TT;
    const int tid = threadIdx.x;

    const int lang = __ldg(lang_ids + b);

    // Load logits tile, transposed: sl[s*TT + t] = logits[t0+t, b, s]
    #pragma unroll
    for (int i = tid; i < TT * S_; i += P_) {
        int t = i >> 8;           // / S_
        int s = i & (S_ - 1);     // % S_
        sl[s * TT + t] = logits[((size_t)(t0 + t) * B_ + b) * S_ + s];
    }
    __syncthreads();

    const uint32_t* bits = g_bits + lang * NW * P_ + tid;   // [w][P] stride P_

    float a0 = PADV, a1 = PADV, a2 = PADV, a3 = PADV;

    #pragma unroll
    for (int w = 0; w < NW; ++w) {
        uint32_t word = __ldg(bits + w * P_);   // coalesced, L1-hot
        const float* base = sl + (w * 32) * TT;
        while (word) {
            int bit = __ffs(word) - 1;
            word &= word - 1;
            float4 v = *(const float4*)(base + bit * TT);
            a0 = fmaxf(a0, v.x);
            a1 = fmaxf(a1, v.y);
            a2 = fmaxf(a2, v.z);
            a3 = fmaxf(a3, v.w);
        }
    }

    // Write out[t0+t, b, p] — coalesced across p
    out[((size_t)(t0 + 0) * B_ + b) * P_ + tid] = a0;
    out[((size_t)(t0 + 1) * B_ + b) * P_ + tid] = a1;
    out[((size_t)(t0 + 2) * B_ + b) * P_ + tid] = a2;
    out[((size_t)(t0 + 3) * B_ + b) * P_ + tid] = a3;
}

// ---------------------------------------------------------------------------
extern "C" void kernel_launch(void* const* d_in, const int* in_sizes, int n_in,
                              void* d_out, int out_size) {
    const float* logits = (const float*)d_in[0];   // [T,B,S] f32
    const int*   langs  = (const int*)  d_in[1];   // [B] i32
    const float* mats   = (const float*)d_in[2];   // [L,S,P] f32
    // d_in[3] (mask) is redundant: mask == (mats == 0)

    build_bits_kernel<<<L_ * NW, P_>>>(mats);      // 128 CTAs

    dim3 grid(T_ / TT, B_);   // 125 x 16
    allophone_map_kernel<<<grid, P_>>>(logits, langs, (float*)d_out);
}